// round 2
// baseline (speedup 1.0000x reference)
#include <cuda_runtime.h>
#include <cuda_fp16.h>
#include <cstdint>
#include <cstddef>

static constexpr int BB = 8, SSQ = 4096, DIN = 256, HH = 512;
static constexpr int M = BB * SSQ;        // 32768
static constexpr int KE = 768;            // [xh|xh|xl] K-concat
static constexpr int NG = 4 * HH;         // 2048
static constexpr float EPSF = 1e-6f;
static constexpr int LCH = 128, NCH = SSQ / LCH, NCHAIN = BB * HH;
static constexpr int PAD = 40;            // smem row stride (halfs)

static __device__ __half g_Ah[(size_t)M * KE];     // 48 MB
static __device__ __half g_Bh[(size_t)NG * KE];    // 3 MB
static __device__ float  g_G[(size_t)M * NG];      // 256 MB gates (i,f,o,z)
static __device__ float  g_Pa[NCHAIN * NCH];
static __device__ float  g_Ci[NCHAIN * NCH];
static __device__ float  g_Ni[NCHAIN * NCH];

__device__ __forceinline__ uint32_t smem_u32(const void* p) {
    uint32_t a;
    asm("{ .reg .u64 t; cvta.to.shared.u64 t, %1; cvt.u32.u64 %0, t; }" : "=r"(a) : "l"(p));
    return a;
}

// ---------------- prep A: [xh | xh | xl], row-major K-contig ----------------
__global__ void xl_prepA(const float* __restrict__ x) {
    int gid = blockIdx.x * blockDim.x + threadIdx.x;       // M*64 threads, 4 k each
    int j = gid & 63, m = gid >> 6;
    int k = j * 4;
    float4 v = *reinterpret_cast<const float4*>(x + (size_t)m * DIN + k);
    __half h[4], l[4];
    float vv[4] = {v.x, v.y, v.z, v.w};
#pragma unroll
    for (int t = 0; t < 4; t++) {
        h[t] = __float2half_rn(vv[t]);
        l[t] = __float2half_rn(vv[t] - __half2float(h[t]));
    }
    __half* row = g_Ah + (size_t)m * KE;
    *reinterpret_cast<uint2*>(row + k)       = *reinterpret_cast<uint2*>(h);
    *reinterpret_cast<uint2*>(row + 256 + k) = *reinterpret_cast<uint2*>(h);
    *reinterpret_cast<uint2*>(row + 512 + k) = *reinterpret_cast<uint2*>(l);
}

// ---------------- prep B: rows n (gate*512+h), cols [Wh | Wl | Wh] ----------
__global__ void xl_prepB(const float* __restrict__ Wi, const float* __restrict__ Wf,
                         const float* __restrict__ Wo, const float* __restrict__ Wz) {
    int gid = blockIdx.x * blockDim.x + threadIdx.x;       // NG*192 threads, 4 keff each
    int j = gid % 192, n = gid / 192;
    int keff = j * 4;
    int reg = keff >> 8;                                   // 0:hi 1:lo 2:hi
    int ks = keff & 255;
    int g = n >> 9, nc = n & 511;
    const float* W = (g == 0) ? Wi : (g == 1) ? Wf : (g == 2) ? Wo : Wz;
    __half out[4];
#pragma unroll
    for (int t = 0; t < 4; t++) {
        float w = W[(size_t)(ks + t) * HH + nc];
        __half hi = __float2half_rn(w);
        out[t] = (reg == 1) ? __float2half_rn(w - __half2float(hi)) : hi;
    }
    *reinterpret_cast<uint2*>(g_Bh + (size_t)n * KE + keff) = *reinterpret_cast<uint2*>(out);
}

// ---------------- GEMM + activation epilogue ----------------
__device__ __forceinline__ uint32_t lds2(const __half* base, int r, int k) {
    return *reinterpret_cast<const uint32_t*>(base + r * PAD + k);
}

__global__ __launch_bounds__(256) void xl_gemm(const float* __restrict__ bi, const float* __restrict__ bfg,
                                               const float* __restrict__ bo, const float* __restrict__ bz) {
    __shared__ __half As[2][128 * PAD];
    __shared__ __half Bs[2][128 * PAD];
    const int tid = threadIdx.x, lane = tid & 31, wid = tid >> 5;
    const int bm = blockIdx.y * 128, bn = blockIdx.x * 128;
    const int warp_m = (wid & 1) * 64, warp_n = (wid >> 1) * 32;
    const int grp = lane >> 2, tq = lane & 3;

    float acc[4][4][4];
#pragma unroll
    for (int a = 0; a < 4; a++)
#pragma unroll
        for (int b = 0; b < 4; b++)
#pragma unroll
            for (int c = 0; c < 4; c++) acc[a][b][c] = 0.f;

    // cp.async tile loader: 512 int4 per tile, 2 per thread per tile
    auto issue = [&](int kt, int buf) {
#pragma unroll
        for (int half_ = 0; half_ < 2; half_++) {
            int idx = tid + half_ * 256;
            int r = idx >> 2, c = idx & 3;
            uint32_t sa = smem_u32(&As[buf][r * PAD + c * 8]);
            const __half* ga = g_Ah + (size_t)(bm + r) * KE + kt * 32 + c * 8;
            asm volatile("cp.async.cg.shared.global [%0], [%1], 16;" :: "r"(sa), "l"(ga));
            uint32_t sb = smem_u32(&Bs[buf][r * PAD + c * 8]);
            const __half* gb = g_Bh + (size_t)(bn + r) * KE + kt * 32 + c * 8;
            asm volatile("cp.async.cg.shared.global [%0], [%1], 16;" :: "r"(sb), "l"(gb));
        }
        asm volatile("cp.async.commit_group;" ::: "memory");
    };

    issue(0, 0);
    const int NKT = KE / 32;   // 24
    for (int kt = 0; kt < NKT; kt++) {
        int buf = kt & 1;
        if (kt + 1 < NKT) {
            issue(kt + 1, buf ^ 1);
            asm volatile("cp.async.wait_group 1;" ::: "memory");
        } else {
            asm volatile("cp.async.wait_group 0;" ::: "memory");
        }
        __syncthreads();
        const __half* Ab = As[buf];
        const __half* Bb = Bs[buf];
#pragma unroll
        for (int ks = 0; ks < 32; ks += 16) {
            uint32_t a[4][4], b[4][2];
#pragma unroll
            for (int im = 0; im < 4; im++) {
                int r0 = warp_m + im * 16 + grp;
                a[im][0] = lds2(Ab, r0,     ks + tq * 2);
                a[im][1] = lds2(Ab, r0 + 8, ks + tq * 2);
                a[im][2] = lds2(Ab, r0,     ks + tq * 2 + 8);
                a[im][3] = lds2(Ab, r0 + 8, ks + tq * 2 + 8);
            }
#pragma unroll
            for (int in = 0; in < 4; in++) {
                int n0 = warp_n + in * 8 + grp;
                b[in][0] = lds2(Bb, n0, ks + tq * 2);
                b[in][1] = lds2(Bb, n0, ks + tq * 2 + 8);
            }
#pragma unroll
            for (int im = 0; im < 4; im++)
#pragma unroll
                for (int in = 0; in < 4; in++) {
                    asm volatile(
                        "mma.sync.aligned.m16n8k16.row.col.f32.f16.f16.f32 "
                        "{%0,%1,%2,%3}, {%4,%5,%6,%7}, {%8,%9}, {%0,%1,%2,%3};"
                        : "+f"(acc[im][in][0]), "+f"(acc[im][in][1]),
                          "+f"(acc[im][in][2]), "+f"(acc[im][in][3])
                        : "r"(a[im][0]), "r"(a[im][1]), "r"(a[im][2]), "r"(a[im][3]),
                          "r"(b[in][0]), "r"(b[in][1]));
                }
        }
        __syncthreads();
    }

    // epilogue: gate constant per block (128 | 512)
    const int g = blockIdx.x >> 2;
    const float* bias = (g == 0) ? bi : (g == 1) ? bfg : (g == 2) ? bo : bz;
#pragma unroll
    for (int im = 0; im < 4; im++)
#pragma unroll
        for (int in = 0; in < 4; in++) {
            int row0 = bm + warp_m + im * 16 + grp;
            int col0 = bn + warp_n + in * 8 + tq * 2;
            float b0 = bias[col0 & (HH - 1)], b1 = bias[(col0 + 1) & (HH - 1)];
#pragma unroll
            for (int hrow = 0; hrow < 2; hrow++) {
                int row = row0 + hrow * 8;
                float a0 = acc[im][in][hrow * 2 + 0] + b0;
                float a1 = acc[im][in][hrow * 2 + 1] + b1;
                float2 o;
                if (g < 2) {
                    o.x = __expf(fminf(fmaxf(a0, -20.f), 0.f));
                    o.y = __expf(fminf(fmaxf(a1, -20.f), 0.f));
                } else if (g == 2) {
                    o.x = 1.f / (1.f + __expf(-a0));
                    o.y = 1.f / (1.f + __expf(-a1));
                } else {
                    o.x = tanhf(a0);
                    o.y = tanhf(a1);
                }
                *reinterpret_cast<float2*>(g_G + (size_t)row * NG + col0) = o;
            }
        }
}

// ---------------- scan pass 1: per-chunk local (P, C, N) ----------------
__global__ void xl_scan1() {
    int t = blockIdx.x * blockDim.x + threadIdx.x;   // 131072
    int h = t & 511, ch = (t >> 9) & 31, b = t >> 14;
    float P = 1.f, C = 0.f, N = 0.f;
    const float* base = g_G + ((size_t)(b * SSQ + ch * LCH)) * NG + h;
    for (int s = 0; s < LCH; s++) {
        const float* p = base + (size_t)s * NG;
        float iv = p[0], fv = p[512], zv = p[1536];
        C = fv * C + iv * zv;
        N = fv * N + iv;
        P *= fv;
    }
    int idx = (b * NCH + ch) * HH + h;
    g_Pa[idx] = P; g_Ci[idx] = C; g_Ni[idx] = N;
}

// ---------------- scan pass 2: chunk-level scan, overwrite with inits -------
__global__ void xl_scan2() {
    int t = blockIdx.x * blockDim.x + threadIdx.x;   // 4096
    int h = t & 511, b = t >> 9;
    float c = 0.f, n = 1.f;
    for (int ch = 0; ch < NCH; ch++) {
        int idx = (b * NCH + ch) * HH + h;
        float P = g_Pa[idx], Cl = g_Ci[idx], Nl = g_Ni[idx];
        g_Ci[idx] = c; g_Ni[idx] = n;
        c = P * c + Cl;
        n = P * n + Nl;
    }
}

// ---------------- scan pass 3: recompute with inits, emit h ----------------
__global__ void xl_scan3(float* __restrict__ out) {
    int t = blockIdx.x * blockDim.x + threadIdx.x;   // 131072
    int h = t & 511, ch = (t >> 9) & 31, b = t >> 14;
    int idx = (b * NCH + ch) * HH + h;
    float c = g_Ci[idx], n = g_Ni[idx];
    const float* base = g_G + ((size_t)(b * SSQ + ch * LCH)) * NG + h;
    float* ob = out + ((size_t)(b * SSQ + ch * LCH)) * HH + h;
    for (int s = 0; s < LCH; s++) {
        const float* p = base + (size_t)s * NG;
        float iv = p[0], fv = p[512], ov = p[1024], zv = p[1536];
        c = fv * c + iv * zv;
        n = fv * n + iv;
        ob[(size_t)s * HH] = ov * (c / (n + EPSF));
    }
}

extern "C" void kernel_launch(void* const* d_in, const int* in_sizes, int n_in,
                              void* d_out, int out_size) {
    const float* x  = (const float*)d_in[0];
    const float* Wi = (const float*)d_in[1];
    const float* bi = (const float*)d_in[2];
    const float* Wf = (const float*)d_in[3];
    const float* bf = (const float*)d_in[4];
    const float* Wo = (const float*)d_in[5];
    const float* bo = (const float*)d_in[6];
    const float* Wz = (const float*)d_in[7];
    const float* bz = (const float*)d_in[8];
    float* out = (float*)d_out;

    xl_prepA<<<(M * 64) / 256, 256>>>(x);
    xl_prepB<<<(NG * 192) / 256, 256>>>(Wi, Wf, Wo, Wz);
    xl_gemm<<<dim3(NG / 128, M / 128), 256>>>(bi, bf, bo, bz);
    xl_scan1<<<(NCHAIN * NCH) / 256, 256>>>();
    xl_scan2<<<NCHAIN / 256, 256>>>();
    xl_scan3<<<(NCHAIN * NCH) / 256, 256>>>(out);
}